// round 10
// baseline (speedup 1.0000x reference)
#include <cuda_runtime.h>
#include <cuda_fp16.h>
#include <math.h>

#define BB 16
#define HH 12
#define NN 784
#define NROWS (BB * NN)        // 12544
#define NSQ (NN * NN)          // 614656
#define NPAIR (NROWS * 49)     // int4 pairs total = 614656
#define NORM_BLOCKS (NPAIR / 256)  // 2401 exactly

// Device-global scratch (allocation is forbidden; __device__ globals are allowed)
__device__ __half g_scratch[(size_t)BB * NSQ];   // exp(x - rowmax), ~19.7 MB
__device__ float2 g_rowstats[NROWS];             // (rowmax, rowsumexp)
__device__ float  g_rowscale[NROWS];             // exp(rowmax - gmax) / sum_b

// ---------------------------------------------------------------------------
// k_agg: EXACT R5/R9-proven version (80.4us, LTS-bound floor). DO NOT TOUCH.
// ---------------------------------------------------------------------------
__global__ __launch_bounds__(384) void k_agg(const float* __restrict__ m) {
    __shared__ float sm[HH * NN];   // 37632 B
    __shared__ float rs[HH];
    __shared__ float red[HH];
    __shared__ float s_bcast;

    const int bi = blockIdx.x;          // b*NN + i
    const int b  = bi / NN;
    const int i  = bi - b * NN;
    const int t    = threadIdx.x;
    const int w    = t >> 5;
    const int lane = t & 31;

    const float4* row = (const float4*)(m + ((size_t)(b * HH + w) * NN + i) * NN);
    float4* smrow = (float4*)(sm + w * NN);
    float s = 0.f;
    #pragma unroll
    for (int j = lane; j < NN / 4; j += 32) {
        float4 v = __ldcs(row + j);
        smrow[j] = v;
        s += (v.x + v.y) + (v.z + v.w);
    }
    #pragma unroll
    for (int o = 16; o; o >>= 1) s += __shfl_xor_sync(0xffffffffu, s, o);
    if (lane == 0) rs[w] = s;
    __syncthreads();

    float rr[HH];
    #pragma unroll
    for (int h = 0; h < HH; h++) rr[h] = rs[h];

    float a0 = 0.f, a1 = 0.f, a2 = 0.f;
    #pragma unroll
    for (int h = 0; h < HH; h++) {
        a0 = fmaf(sm[h * NN + t],       rr[h], a0);
        a1 = fmaf(sm[h * NN + t + 384], rr[h], a1);
    }
    if (t < 16) {
        #pragma unroll
        for (int h = 0; h < HH; h++) a2 = fmaf(sm[h * NN + t + 768], rr[h], a2);
    }

    float mx = fmaxf(a0, a1);
    if (t < 16) mx = fmaxf(mx, a2);
    #pragma unroll
    for (int o = 16; o; o >>= 1) mx = fmaxf(mx, __shfl_xor_sync(0xffffffffu, mx, o));
    if (lane == 0) red[w] = mx;
    __syncthreads();
    if (t == 0) {
        float M = red[0];
        #pragma unroll
        for (int h = 1; h < HH; h++) M = fmaxf(M, red[h]);
        s_bcast = M;
    }
    __syncthreads();
    const float rowmax = s_bcast;

    __half* srow = g_scratch + (size_t)bi * NN;
    float e0 = expf(a0 - rowmax);
    float e1 = expf(a1 - rowmax);
    srow[t]       = __float2half_rn(e0);
    srow[t + 384] = __float2half_rn(e1);
    float sume = e0 + e1;
    if (t < 16) {
        float e2 = expf(a2 - rowmax);
        srow[t + 768] = __float2half_rn(e2);
        sume += e2;
    }
    #pragma unroll
    for (int o = 16; o; o >>= 1) sume += __shfl_xor_sync(0xffffffffu, sume, o);
    if (lane == 0) red[w] = sume;
    __syncthreads();
    if (t == 0) {
        float S = 0.f;
        #pragma unroll
        for (int h = 0; h < HH; h++) S += red[h];
        g_rowstats[bi] = make_float2(rowmax, S);
    }
}

// ---------------------------------------------------------------------------
// k_combine: EXACT R9-proven version. One block per batch, 784 active threads.
// ---------------------------------------------------------------------------
__global__ __launch_bounds__(800) void k_combine() {
    const int b = blockIdx.x;
    const int t = threadIdx.x;
    __shared__ float red[25];
    __shared__ float s_gmax, s_inv;

    const bool act = (t < NN);
    float2 st = act ? g_rowstats[b * NN + t] : make_float2(-1e30f, 0.f);

    float mx = st.x;
    #pragma unroll
    for (int o = 16; o; o >>= 1) mx = fmaxf(mx, __shfl_xor_sync(0xffffffffu, mx, o));
    if ((t & 31) == 0) red[t >> 5] = mx;
    __syncthreads();
    if (t == 0) {
        float M = red[0];
        #pragma unroll
        for (int k = 1; k < 25; k++) M = fmaxf(M, red[k]);
        s_gmax = M;
    }
    __syncthreads();
    const float gmax = s_gmax;

    float s = act ? st.y * expf(st.x - gmax) : 0.f;
    #pragma unroll
    for (int o = 16; o; o >>= 1) s += __shfl_xor_sync(0xffffffffu, s, o);
    __syncthreads();
    if ((t & 31) == 0) red[t >> 5] = s;
    __syncthreads();
    if (t == 0) {
        float S = 0.f;
        #pragma unroll
        for (int k = 0; k < 25; k++) S += red[k];
        s_inv = 1.f / S;
    }
    __syncthreads();

    if (act) g_rowscale[b * NN + t] = expf(st.x - gmax) * s_inv;
}

// ---------------------------------------------------------------------------
// k_norm: pair-per-thread, PLAIN stores (the R8 variant minus __stcs, which
// the R7/R8 evidence implicates). Each thread: 2 consecutive int4 of one row
// (49 pairs/row -> never straddles rows), 1 scale fetch, 4 float4 stores.
// 614656 pairs = 2401 blocks * 256 exactly.
// ---------------------------------------------------------------------------
__global__ __launch_bounds__(256) void k_norm(float* __restrict__ out) {
    const int p   = blockIdx.x * 256 + threadIdx.x;   // pair index
    const int row = p / 49;
    const float sc = g_rowscale[row];

    const int4* src = ((const int4*)g_scratch) + 2 * p;
    int4 v0 = src[0];
    int4 v1 = src[1];

    float4* dst = ((float4*)out) + 4 * p;
    {
        float2 f0 = __half22float2(*(__half2*)&v0.x);
        float2 f1 = __half22float2(*(__half2*)&v0.y);
        float2 f2 = __half22float2(*(__half2*)&v0.z);
        float2 f3 = __half22float2(*(__half2*)&v0.w);
        dst[0] = make_float4(f0.x * sc, f0.y * sc, f1.x * sc, f1.y * sc);
        dst[1] = make_float4(f2.x * sc, f2.y * sc, f3.x * sc, f3.y * sc);
    }
    {
        float2 f0 = __half22float2(*(__half2*)&v1.x);
        float2 f1 = __half22float2(*(__half2*)&v1.y);
        float2 f2 = __half22float2(*(__half2*)&v1.z);
        float2 f3 = __half22float2(*(__half2*)&v1.w);
        dst[2] = make_float4(f0.x * sc, f0.y * sc, f1.x * sc, f1.y * sc);
        dst[3] = make_float4(f2.x * sc, f2.y * sc, f3.x * sc, f3.y * sc);
    }
}

// ---------------------------------------------------------------------------
extern "C" void kernel_launch(void* const* d_in, const int* in_sizes, int n_in,
                              void* d_out, int out_size) {
    const float* m = (const float*)d_in[0];
    float* out = (float*)d_out;

    k_agg<<<NROWS, 384>>>(m);
    k_combine<<<BB, 800>>>();
    k_norm<<<NORM_BLOCKS, 256>>>(out);
}

// round 11
// speedup vs baseline: 1.0283x; 1.0283x over previous
#include <cuda_runtime.h>
#include <cuda_fp16.h>
#include <math.h>

#define BB 16
#define HH 12
#define NN 784
#define NROWS (BB * NN)        // 12544
#define NSQ (NN * NN)          // 614656

// Device-global scratch (allocation is forbidden; __device__ globals are allowed)
__device__ __half g_scratch[(size_t)BB * NSQ];   // exp(x - rowmax), ~19.7 MB
__device__ float2 g_rowstats[NROWS];             // (rowmax, rowsumexp)
__device__ float  g_rowscale[NROWS];             // exp(rowmax - gmax) / sum_b

// ---------------------------------------------------------------------------
// k_agg: R5/R9-proven (80.3us, 6.0 TB/s — LTS-cap bound). One block per
// (b,i); 12 warps stage the 12 head rows in SMEM (+rowsums); block computes
// agg[l] = sum_h m[h][l]*rowsum[h], row max, exp (fp16 to scratch), row
// expsum, per-row stats. __ldcs on the touch-once input stream keeps the
// L2-resident scratch from being evicted (proven R5 win).
// ---------------------------------------------------------------------------
__global__ __launch_bounds__(384) void k_agg(const float* __restrict__ m) {
    __shared__ float sm[HH * NN];   // 37632 B
    __shared__ float rs[HH];
    __shared__ float red[HH];
    __shared__ float s_bcast;

    const int bi = blockIdx.x;          // b*NN + i
    const int b  = bi / NN;
    const int i  = bi - b * NN;
    const int t    = threadIdx.x;
    const int w    = t >> 5;
    const int lane = t & 31;

    const float4* row = (const float4*)(m + ((size_t)(b * HH + w) * NN + i) * NN);
    float4* smrow = (float4*)(sm + w * NN);
    float s = 0.f;
    #pragma unroll
    for (int j = lane; j < NN / 4; j += 32) {
        float4 v = __ldcs(row + j);
        smrow[j] = v;
        s += (v.x + v.y) + (v.z + v.w);
    }
    #pragma unroll
    for (int o = 16; o; o >>= 1) s += __shfl_xor_sync(0xffffffffu, s, o);
    if (lane == 0) rs[w] = s;
    __syncthreads();

    float rr[HH];
    #pragma unroll
    for (int h = 0; h < HH; h++) rr[h] = rs[h];

    float a0 = 0.f, a1 = 0.f, a2 = 0.f;
    #pragma unroll
    for (int h = 0; h < HH; h++) {
        a0 = fmaf(sm[h * NN + t],       rr[h], a0);
        a1 = fmaf(sm[h * NN + t + 384], rr[h], a1);
    }
    if (t < 16) {
        #pragma unroll
        for (int h = 0; h < HH; h++) a2 = fmaf(sm[h * NN + t + 768], rr[h], a2);
    }

    float mx = fmaxf(a0, a1);
    if (t < 16) mx = fmaxf(mx, a2);
    #pragma unroll
    for (int o = 16; o; o >>= 1) mx = fmaxf(mx, __shfl_xor_sync(0xffffffffu, mx, o));
    if (lane == 0) red[w] = mx;
    __syncthreads();
    if (t == 0) {
        float M = red[0];
        #pragma unroll
        for (int h = 1; h < HH; h++) M = fmaxf(M, red[h]);
        s_bcast = M;
    }
    __syncthreads();
    const float rowmax = s_bcast;

    __half* srow = g_scratch + (size_t)bi * NN;
    float e0 = expf(a0 - rowmax);
    float e1 = expf(a1 - rowmax);
    srow[t]       = __float2half_rn(e0);
    srow[t + 384] = __float2half_rn(e1);
    float sume = e0 + e1;
    if (t < 16) {
        float e2 = expf(a2 - rowmax);
        srow[t + 768] = __float2half_rn(e2);
        sume += e2;
    }
    #pragma unroll
    for (int o = 16; o; o >>= 1) sume += __shfl_xor_sync(0xffffffffu, sume, o);
    if (lane == 0) red[w] = sume;
    __syncthreads();
    if (t == 0) {
        float S = 0.f;
        #pragma unroll
        for (int h = 0; h < HH; h++) S += red[h];
        g_rowstats[bi] = make_float2(rowmax, S);
    }
}

// ---------------------------------------------------------------------------
// k_combine: R9-proven. One block per batch, 784 active threads (one row
// each); 2-phase tree reduction -> gmax, 1/sum; per-row scale. Deterministic.
// ---------------------------------------------------------------------------
__global__ __launch_bounds__(800) void k_combine() {
    const int b = blockIdx.x;
    const int t = threadIdx.x;
    __shared__ float red[25];
    __shared__ float s_gmax, s_inv;

    const bool act = (t < NN);
    float2 st = act ? g_rowstats[b * NN + t] : make_float2(-1e30f, 0.f);

    float mx = st.x;
    #pragma unroll
    for (int o = 16; o; o >>= 1) mx = fmaxf(mx, __shfl_xor_sync(0xffffffffu, mx, o));
    if ((t & 31) == 0) red[t >> 5] = mx;
    __syncthreads();
    if (t == 0) {
        float M = red[0];
        #pragma unroll
        for (int k = 1; k < 25; k++) M = fmaxf(M, red[k]);
        s_gmax = M;
    }
    __syncthreads();
    const float gmax = s_gmax;

    float s = act ? st.y * expf(st.x - gmax) : 0.f;
    #pragma unroll
    for (int o = 16; o; o >>= 1) s += __shfl_xor_sync(0xffffffffu, s, o);
    __syncthreads();
    if ((t & 31) == 0) red[t >> 5] = s;
    __syncthreads();
    if (t == 0) {
        float S = 0.f;
        #pragma unroll
        for (int k = 0; k < 25; k++) S += red[k];
        s_inv = 1.f / S;
    }
    __syncthreads();

    if (act) g_rowscale[b * NN + t] = expf(st.x - gmax) * s_inv;
}

// ---------------------------------------------------------------------------
// k_norm: R5/R9-proven local optimum (beat MLP-chains, pair-per-thread with
// and without __stcs, and fused-combine variants head-to-head). One int4
// (8 halves) -> 2 float4 per thread, plain stores.
// Total int4 = 1,229,312 = 4802 blocks * 256 exactly.
// ---------------------------------------------------------------------------
__global__ __launch_bounds__(256) void k_norm(float* __restrict__ out) {
    const int j = blockIdx.x * 256 + threadIdx.x;   // int4 index
    const int row = j / 98;                          // 98 int4 per row (784/8)
    const float sc = g_rowscale[row];

    int4 v = ((const int4*)g_scratch)[j];
    float2 f0 = __half22float2(*(__half2*)&v.x);
    float2 f1 = __half22float2(*(__half2*)&v.y);
    float2 f2 = __half22float2(*(__half2*)&v.z);
    float2 f3 = __half22float2(*(__half2*)&v.w);

    float4 o0 = make_float4(f0.x * sc, f0.y * sc, f1.x * sc, f1.y * sc);
    float4 o1 = make_float4(f2.x * sc, f2.y * sc, f3.x * sc, f3.y * sc);
    ((float4*)out)[2 * j]     = o0;
    ((float4*)out)[2 * j + 1] = o1;
}

// ---------------------------------------------------------------------------
extern "C" void kernel_launch(void* const* d_in, const int* in_sizes, int n_in,
                              void* d_out, int out_size) {
    const float* m = (const float*)d_in[0];
    float* out = (float*)d_out;

    k_agg<<<NROWS, 384>>>(m);
    k_combine<<<BB, 800>>>();
    k_norm<<<4802, 256>>>(out);
}